// round 16
// baseline (speedup 1.0000x reference)
#include <cuda_runtime.h>

// Problem constants (fixed by the reference setup)
#define BB 64
#define SS 1024
#define DD 32
#define HH 2
#define DH 16
#define VV 28
#define LOG2E 1.44269504088896340736f
#define KC 256      // keys per split-K chunk
#define NKC_MAX 4   // max key chunks  (SS/KC)
#define NQT_MAX 8   // max 128-query tiles (SS/128)
#define TS 36       // token stage stride in floats (multiple of 4 -> aligned)

#define NQ (BB * HH * SS * DH)

typedef unsigned long long u64;

// Scratch (no allocations allowed -> __device__ globals), 16B-aligned
// Q stored row-major [bh][s][16] as tf32 hi/lo planes (exact split hi+lo ~ q)
__device__ __align__(16) float g_Qhi[NQ];
__device__ __align__(16) float g_Qlo[NQ];
__device__ __align__(16) float g_K[NQ];     // row-major [bh][s][16], fp32
__device__ __align__(16) float g_V[NQ];
// split-K partials, tile-SoA: [bh][kc][qt][j:4][128] float4 + [bh][kc][qt][128]
__device__ __align__(16) float g_Po[(size_t)BB * HH * NKC_MAX * NQT_MAX * 128 * DH];
__device__ __align__(16) float g_Pl[(size_t)BB * HH * NKC_MAX * NQT_MAX * 128];
__device__ int   g_Lb[BB];
__device__ __align__(16) float g_wc[VV * DD];
__device__ float g_bc[VV];

// ---------------------------------------------------------------------------
// Packed f32x2 + tf32 + misc PTX helpers
// ---------------------------------------------------------------------------
__device__ __forceinline__ u64 fma2(u64 a, u64 b, u64 c) {
    u64 d; asm("fma.rn.f32x2 %0,%1,%2,%3;" : "=l"(d) : "l"(a), "l"(b), "l"(c));
    return d;
}
__device__ __forceinline__ u64 mul2(u64 a, u64 b) {
    u64 d; asm("mul.rn.f32x2 %0,%1,%2;" : "=l"(d) : "l"(a), "l"(b));
    return d;
}
__device__ __forceinline__ u64 add2(u64 a, u64 b) {
    u64 d; asm("add.rn.f32x2 %0,%1,%2;" : "=l"(d) : "l"(a), "l"(b));
    return d;
}
__device__ __forceinline__ u64 pack2(float x, float y) {
    u64 r; asm("mov.b64 %0,{%1,%2};" : "=l"(r) : "f"(x), "f"(y));
    return r;
}
__device__ __forceinline__ float2 unpk(u64 v) {
    float2 r; asm("mov.b64 {%0,%1},%2;" : "=f"(r.x), "=f"(r.y) : "l"(v));
    return r;
}
__device__ __forceinline__ float ex2(float x) {
    float r; asm("ex2.approx.f32 %0,%1;" : "=f"(r) : "f"(x));
    return r;
}
__device__ __forceinline__ unsigned tf32u(float x) {
    unsigned r; asm("cvt.rna.tf32.f32 %0,%1;" : "=r"(r) : "f"(x));
    return r;
}
// D += A(tf32) * B(tf32), m16n8k8, A row-major, B col-major, f32 accumulate
__device__ __forceinline__ void mma8(float& d0, float& d1, float& d2, float& d3,
                                     const unsigned a[4], unsigned b0, unsigned b1) {
    asm volatile(
        "mma.sync.aligned.m16n8k8.row.col.f32.tf32.tf32.f32 "
        "{%0,%1,%2,%3},{%4,%5,%6,%7},{%8,%9},{%0,%1,%2,%3};"
        : "+f"(d0), "+f"(d1), "+f"(d2), "+f"(d3)
        : "r"(a[0]), "r"(a[1]), "r"(a[2]), "r"(a[3]), "r"(b0), "r"(b1));
}

// ---------------------------------------------------------------------------
// K0: per-batch prefix length Lb + combined output weights wc = w_fc @ wo
// ---------------------------------------------------------------------------
__global__ void prep_kernel(const float* __restrict__ mask,
                            const float* __restrict__ wo,
                            const float* __restrict__ bo,
                            const float* __restrict__ wfc,
                            const float* __restrict__ bfc) {
    int tid = threadIdx.x;
    int bb  = blockIdx.x;
    if (bb < BB) {
        __shared__ int smax[256];
        int mx = -1;
        const float* mp = mask + bb * SS;
        for (int s = tid; s < SS; s += 256)
            if (mp[s] > 0.f) mx = max(mx, s);
        smax[tid] = mx;
        __syncthreads();
        for (int off = 128; off > 0; off >>= 1) {
            if (tid < off) smax[tid] = max(smax[tid], smax[tid + off]);
            __syncthreads();
        }
        if (tid == 0) g_Lb[bb] = min(smax[0] + 4, SS - 1);
    } else {
        for (int e = tid; e < VV * DD; e += 256) {
            int v = e >> 5, d = e & 31;
            float acc = 0.f;
            #pragma unroll
            for (int t = 0; t < 32; t++)
                acc += wfc[v * 32 + t] * wo[t * 32 + d];
            g_wc[e] = acc;
        }
        if (tid < VV) {
            float acc = bfc[tid];
            #pragma unroll
            for (int t = 0; t < 32; t++)
                acc += wfc[tid * 32 + t] * bo[t];
            g_bc[tid] = acc;
        }
    }
}

// ---------------------------------------------------------------------------
// K1: QKV projections, 256 tokens/block (one batch b). One weight matrix
//     staged in smem at a time. Q pre-scaled by 0.25*log2e and split into
//     exact tf32 hi/lo planes (row-major). K/V row-major fp32. All writes
//     coalesced via the padded smem stage.
// ---------------------------------------------------------------------------
__global__ void __launch_bounds__(256) qkv_kernel(
    const int* __restrict__ x,  const float* __restrict__ emb,
    const float* __restrict__ pe,
    const float* __restrict__ wq, const float* __restrict__ bq,
    const float* __restrict__ wk, const float* __restrict__ bk,
    const float* __restrict__ wv, const float* __restrict__ bv) {

    __shared__ __align__(16) float sw[1024 + 32];
    __shared__ __align__(16) float so[256 * TS];     // 36 KB
    int tid = threadIdx.x;

    int t0 = blockIdx.x * 256;
    int b  = t0 >> 10, s0 = t0 & 1023;
    int s  = s0 + tid;
    int Lb = g_Lb[b];
    const float QSCL = 0.25f * LOG2E;
    bool live = (s < Lb);

    u64 h2[16];
    if (live) {
        int xid = x[t0 + tid];
        const float4* ep = (const float4*)(emb + xid * 32);
        const float4* pp = (const float4*)(pe + s * 32);
        #pragma unroll
        for (int j = 0; j < 8; j++) {
            float4 e4 = ep[j], p4 = pp[j];
            h2[2 * j]     = pack2(e4.x + p4.x, e4.y + p4.y);
            h2[2 * j + 1] = pack2(e4.z + p4.z, e4.w + p4.w);
        }
    }

    #pragma unroll
    for (int mtx = 0; mtx < 3; mtx++) {
        const float* wg = (mtx == 0) ? wq : ((mtx == 1) ? wk : wv);
        const float* bg = (mtx == 0) ? bq : ((mtx == 1) ? bk : bv);
        float scl = (mtx == 0) ? QSCL : 1.0f;

        for (int i = tid; i < 1024; i += 256) sw[i] = wg[i];
        if (tid < 32) sw[1024 + tid] = bg[tid];
        __syncthreads();

        if (live) {
            #pragma unroll 4
            for (int j = 0; j < 32; j++) {
                const ulonglong2* wr = (const ulonglong2*)(sw + j * 32);
                ulonglong2 w0 = wr[0], w1 = wr[1], w2 = wr[2], w3 = wr[3];
                ulonglong2 w4 = wr[4], w5 = wr[5], w6 = wr[6], w7 = wr[7];
                u64 a0 = mul2(h2[0], w0.x);
                u64 a1 = mul2(h2[1], w0.y);
                a0 = fma2(h2[2],  w1.x, a0);  a1 = fma2(h2[3],  w1.y, a1);
                a0 = fma2(h2[4],  w2.x, a0);  a1 = fma2(h2[5],  w2.y, a1);
                a0 = fma2(h2[6],  w3.x, a0);  a1 = fma2(h2[7],  w3.y, a1);
                a0 = fma2(h2[8],  w4.x, a0);  a1 = fma2(h2[9],  w4.y, a1);
                a0 = fma2(h2[10], w5.x, a0);  a1 = fma2(h2[11], w5.y, a1);
                a0 = fma2(h2[12], w6.x, a0);  a1 = fma2(h2[13], w6.y, a1);
                a0 = fma2(h2[14], w7.x, a0);  a1 = fma2(h2[15], w7.y, a1);
                float2 p = unpk(add2(a0, a1));
                so[tid * TS + j] = (p.x + p.y + sw[1024 + j]) * scl;
            }
        } else {
            #pragma unroll 4
            for (int j = 0; j < 32; j++)
                so[tid * TS + j] = sw[1024 + j] * scl;  // tail Q row; K/V unread
        }
        __syncthreads();

        if (mtx == 0) {
            // Q: split into tf32 hi/lo, write row-major coalesced
            float4* Qh4 = (float4*)g_Qhi;
            float4* Ql4 = (float4*)g_Qlo;
            #pragma unroll
            for (int r = 0; r < 8; r++) {
                int i = tid + r * 256;
                int hh = i >> 10, low = i & 1023;   // low = tok*4+qq
                float4 v = *(const float4*)(so + (low >> 2) * TS + hh * 16 + (low & 3) * 4);
                float4 h, lo;
                h.x = __uint_as_float(tf32u(v.x)); lo.x = __uint_as_float(tf32u(v.x - h.x));
                h.y = __uint_as_float(tf32u(v.y)); lo.y = __uint_as_float(tf32u(v.y - h.y));
                h.z = __uint_as_float(tf32u(v.z)); lo.z = __uint_as_float(tf32u(v.z - h.z));
                h.w = __uint_as_float(tf32u(v.w)); lo.w = __uint_as_float(tf32u(v.w - h.w));
                size_t addr = ((size_t)(b * 2 + hh) * SS + s0) * 4 + low;
                Qh4[addr] = h;
                Ql4[addr] = lo;
            }
        } else {
            float4* outp = (float4*)((mtx == 1) ? g_K : g_V);
            #pragma unroll
            for (int r = 0; r < 8; r++) {
                int i = tid + r * 256;
                int hh = i >> 10, low = i & 1023;
                outp[((size_t)(b * 2 + hh) * SS + s0) * 4 + low] =
                    *(const float4*)(so + (low >> 2) * TS + hh * 16 + (low & 3) * 4);
            }
        }
        __syncthreads();
    }
}

// ---------------------------------------------------------------------------
// K2: split-K attention, tensor-core QK^T (tf32 3-term hi/lo = fp32-exact)
//     + scalar fp32 PV. Block = 128 threads (4 warps), tile 128q x 256k.
//     Grid (B*H, NQT_MAX, NKC_MAX); dead tiles early-exit. Partials written
//     in the same tile-SoA planes; finish_kernel unchanged.
// ---------------------------------------------------------------------------
__global__ void __launch_bounds__(128, 3) attn_kernel() {
    __shared__ __align__(16) float sK[KC * DH];     // 16 KB fp32 keys
    __shared__ __align__(16) float sV[KC * DH];     // 16 KB fp32 values
    __shared__ __align__(16) float sQh[128 * DH];   // 8 KB  tf32-hi queries
    __shared__ __align__(16) float sQl[128 * DH];   // 8 KB  tf32-lo queries

    int bh = blockIdx.x, qt = blockIdx.y, kc = blockIdx.z;
    int b  = bh >> 1;
    int tid = threadIdx.x;
    int Lb = g_Lb[b];
    int nqt = (Lb >> 7) + 1;             // query tiles cover [0, Lb] inclusive
    int nkc = (Lb + KC - 1) >> 8;        // key chunks over [0, Lb)
    if (qt >= nqt || kc >= nkc) return;

    int k0 = kc << 8;
    int nk = min(KC, Lb - k0);

    // stage K/V (zero-fill beyond nk) and the Q hi/lo tile (all coalesced)
    {
        const float4* Kg = (const float4*)(g_K + ((size_t)bh * SS + k0) * DH);
        const float4* Vg = (const float4*)(g_V + ((size_t)bh * SS + k0) * DH);
        int nf = nk * 4;
        float4 z = make_float4(0.f, 0.f, 0.f, 0.f);
        for (int i = tid; i < KC * 4; i += 128) {
            ((float4*)sK)[i] = (i < nf) ? Kg[i] : z;
            ((float4*)sV)[i] = (i < nf) ? Vg[i] : z;
        }
        const float4* Qh = (const float4*)(g_Qhi + ((size_t)bh * SS + qt * 128) * DH);
        const float4* Ql = (const float4*)(g_Qlo + ((size_t)bh * SS + qt * 128) * DH);
        for (int i = tid; i < 512; i += 128) {
            ((float4*)sQh)[i] = Qh[i];
            ((float4*)sQl)[i] = Ql[i];
        }
    }
    __syncthreads();

    int wid = tid >> 5, lane = tid & 31;
    int gid = lane >> 2, tig = lane & 3;

    // A fragments (Q hi/lo), persistent across all key tiles
    unsigned Ah[2][2][4], Al[2][2][4];
    #pragma unroll
    for (int rb = 0; rb < 2; rb++) {
        #pragma unroll
        for (int db = 0; db < 2; db++) {
            int r0 = wid * 32 + rb * 16 + gid;
            int c0 = db * 8 + tig;
            Ah[rb][db][0] = __float_as_uint(sQh[r0 * 16 + c0]);
            Ah[rb][db][1] = __float_as_uint(sQh[(r0 + 8) * 16 + c0]);
            Ah[rb][db][2] = __float_as_uint(sQh[r0 * 16 + c0 + 4]);
            Ah[rb][db][3] = __float_as_uint(sQh[(r0 + 8) * 16 + c0 + 4]);
            Al[rb][db][0] = __float_as_uint(sQl[r0 * 16 + c0]);
            Al[rb][db][1] = __float_as_uint(sQl[(r0 + 8) * 16 + c0]);
            Al[rb][db][2] = __float_as_uint(sQl[r0 * 16 + c0 + 4]);
            Al[rb][db][3] = __float_as_uint(sQl[(r0 + 8) * 16 + c0 + 4]);
        }
    }

    // accumulators: 4 row-slots x 16 dims (this thread's key-columns only)
    u64 o[4][8];
    float l[4] = {0.f, 0.f, 0.f, 0.f};
    #pragma unroll
    for (int ss = 0; ss < 4; ss++)
        #pragma unroll
        for (int j = 0; j < 8; j++) o[ss][j] = 0ull;

    for (int ct = 0; ct < KC / 8; ct++) {
        // B fragments: K row (ct*8+gid), dims db*8+tig / +4, tf32 hi/lo
        unsigned Bh[2][2], Bl[2][2];
        #pragma unroll
        for (int db = 0; db < 2; db++) {
            float kf0 = sK[(ct * 8 + gid) * 16 + db * 8 + tig];
            float kf1 = sK[(ct * 8 + gid) * 16 + db * 8 + tig + 4];
            unsigned h0 = tf32u(kf0), h1 = tf32u(kf1);
            Bh[db][0] = h0;  Bh[db][1] = h1;
            Bl[db][0] = tf32u(kf0 - __uint_as_float(h0));
            Bl[db][1] = tf32u(kf1 - __uint_as_float(h1));
        }
        // V rows for this thread's two key-columns (quad-broadcast in smem)
        int colA = ct * 8 + 2 * tig;
        const u64* va = (const u64*)(sV + colA * 16);
        const u64* vb = (const u64*)(sV + (colA + 1) * 16);
        u64 VA[8], VB[8];
        #pragma unroll
        for (int j = 0; j < 8; j++) { VA[j] = va[j]; VB[j] = vb[j]; }
        bool okA = colA < nk, okB = colA + 1 < nk;

        #pragma unroll
        for (int rb = 0; rb < 2; rb++) {
            float s0 = 0.f, s1 = 0.f, s2 = 0.f, s3 = 0.f;
            float t0 = 0.f, t1 = 0.f, t2 = 0.f, t3 = 0.f;
            // 3-term tf32: qh*kh (2 db) + ql*kh + qh*kl  (two chains for ILP)
            mma8(s0, s1, s2, s3, Ah[rb][0], Bh[0][0], Bh[0][1]);
            mma8(t0, t1, t2, t3, Ah[rb][1], Bh[1][0], Bh[1][1]);
            mma8(s0, s1, s2, s3, Al[rb][0], Bh[0][0], Bh[0][1]);
            mma8(t0, t1, t2, t3, Al[rb][1], Bh[1][0], Bh[1][1]);
            mma8(s0, s1, s2, s3, Ah[rb][0], Bl[0][0], Bl[0][1]);
            mma8(t0, t1, t2, t3, Ah[rb][1], Bl[1][0], Bl[1][1]);
            float e0 = okA ? ex2(s0 + t0) : 0.f;
            float e1 = okB ? ex2(s1 + t1) : 0.f;
            float e2 = okA ? ex2(s2 + t2) : 0.f;
            float e3 = okB ? ex2(s3 + t3) : 0.f;
            l[rb * 2]     += e0 + e1;
            l[rb * 2 + 1] += e2 + e3;
            u64 e0p = pack2(e0, e0), e1p = pack2(e1, e1);
            u64 e2p = pack2(e2, e2), e3p = pack2(e3, e3);
            #pragma unroll
            for (int j = 0; j < 8; j++) {
                o[rb * 2][j]     = fma2(e0p, VA[j], fma2(e1p, VB[j], o[rb * 2][j]));
                o[rb * 2 + 1][j] = fma2(e2p, VA[j], fma2(e3p, VB[j], o[rb * 2 + 1][j]));
            }
        }
    }

    // reduce o,l across the 4 threads of each row group (butterfly in quads)
    #pragma unroll
    for (int ss = 0; ss < 4; ss++) {
        l[ss] += __shfl_xor_sync(0xffffffffu, l[ss], 1);
        l[ss] += __shfl_xor_sync(0xffffffffu, l[ss], 2);
        #pragma unroll
        for (int j = 0; j < 8; j++) {
            o[ss][j] = add2(o[ss][j], __shfl_xor_sync(0xffffffffu, o[ss][j], 1));
            o[ss][j] = add2(o[ss][j], __shfl_xor_sync(0xffffffffu, o[ss][j], 2));
        }
    }

    __syncthreads();                 // done with sK -> reuse as staging
    float* stage = sK;               // [128 rows][20 floats]
    if (tig == 0) {
        #pragma unroll
        for (int ss = 0; ss < 4; ss++) {
            int row = wid * 32 + (ss >> 1) * 16 + gid + (ss & 1) * 8;
            float* d = stage + row * 20;
            #pragma unroll
            for (int j = 0; j < 8; j++) {
                float2 p = unpk(o[ss][j]);
                d[2 * j] = p.x;  d[2 * j + 1] = p.y;
            }
            d[16] = l[ss];
        }
    }
    __syncthreads();

    // coalesced partial write (tile-SoA planes, deterministic slot)
    size_t slot = ((size_t)(bh * NKC_MAX + kc) * NQT_MAX + qt);
    float4* Po = (float4*)g_Po + slot * 4 * 128;
    #pragma unroll
    for (int j = 0; j < 4; j++)
        Po[j * 128 + tid] = *(const float4*)(stage + tid * 20 + j * 4);
    g_Pl[slot * 128 + tid] = stage[tid * 20 + 16];
}

// ---------------------------------------------------------------------------
// K3: finish = reduce partials + normalize + output GEMM, fused.
//     Block = 256 threads = 128 tokens (2 threads/token, one per head).
//     Tail tokens (s >= qlim) remap to representative row (Lb>>7, Lb&127).
// ---------------------------------------------------------------------------
__global__ void __launch_bounds__(256) finish_kernel(float* __restrict__ out) {
    __shared__ __align__(16) float swc[VV * DD];
    __shared__ float sbc[VV];
    __shared__ __align__(16) float stok[128 * TS];
    __shared__ __align__(16) float sout[128 * VV];

    int tid = threadIdx.x;
    for (int i = tid; i < VV * DD; i += 256) swc[i] = g_wc[i];
    if (tid < VV) sbc[tid] = g_bc[tid];

    int t0 = blockIdx.x * 128;
    int b  = t0 >> 10, s0 = t0 & 1023;
    int qt = s0 >> 7;
    int Lb = g_Lb[b];
    int nkc  = (Lb + KC - 1) >> 8;
    int qlim = ((Lb >> 7) + 1) << 7;   // rows [0, qlim) were computed

    int tok = tid >> 1, half = tid & 1;
    int bh  = b * 2 + half;
    int s   = s0 + tok;
    int qt_e, tk_e;
    if (s < qlim) { qt_e = qt;      tk_e = tok; }
    else          { qt_e = Lb >> 7; tk_e = Lb & 127; }

    // sum partials for this (token, head) -- coalesced within j-planes
    float l = 0.f;
    float4 o0 = make_float4(0, 0, 0, 0), o1 = o0, o2 = o0, o3 = o0;
    #pragma unroll 4
    for (int kc = 0; kc < nkc; kc++) {
        size_t slot = ((size_t)(bh * NKC_MAX + kc) * NQT_MAX + qt_e);
        const float4* Po = (const float4*)g_Po + slot * 4 * 128;
        float4 t0v = Po[0 * 128 + tk_e], t1v = Po[1 * 128 + tk_e];
        float4 t2v = Po[2 * 128 + tk_e], t3v = Po[3 * 128 + tk_e];
        o0.x += t0v.x; o0.y += t0v.y; o0.z += t0v.z; o0.w += t0v.w;
        o1.x += t1v.x; o1.y += t1v.y; o1.z += t1v.z; o1.w += t1v.w;
        o2.x += t2v.x; o2.y += t2v.y; o2.z += t2v.z; o2.w += t2v.w;
        o3.x += t3v.x; o3.y += t3v.y; o3.z += t3v.z; o3.w += t3v.w;
        l += g_Pl[slot * 128 + tk_e];
    }
    float inv = 1.f / l;
    float* dst = stok + tok * TS + half * 16;
    *(float4*)(dst + 0)  = make_float4(o0.x * inv, o0.y * inv, o0.z * inv, o0.w * inv);
    *(float4*)(dst + 4)  = make_float4(o1.x * inv, o1.y * inv, o1.z * inv, o1.w * inv);
    *(float4*)(dst + 8)  = make_float4(o2.x * inv, o2.y * inv, o2.z * inv, o2.w * inv);
    *(float4*)(dst + 12) = make_float4(o3.x * inv, o3.y * inv, o3.z * inv, o3.w * inv);
    __syncthreads();

    // output GEMM: each half computes 14 full-width outputs
    u64 o2r[16];
    const u64* src = (const u64*)(stok + tok * TS);
    #pragma unroll
    for (int j = 0; j < 16; j++) o2r[j] = src[j];

    #pragma unroll 2
    for (int vi = 0; vi < 14; vi++) {
        int v = half * 14 + vi;
        const ulonglong2* wr = (const ulonglong2*)(swc + v * 32);
        ulonglong2 w0 = wr[0], w1 = wr[1], w2 = wr[2], w3 = wr[3];
        ulonglong2 w4 = wr[4], w5 = wr[5], w6 = wr[6], w7 = wr[7];
        u64 a0 = mul2(o2r[0], w0.x);
        u64 a1 = mul2(o2r[1], w0.y);
        a0 = fma2(o2r[2],  w1.x, a0);  a1 = fma2(o2r[3],  w1.y, a1);
        a0 = fma2(o2r[4],  w2.x, a0);  a1 = fma2(o2r[5],  w2.y, a1);
        a0 = fma2(o2r[6],  w3.x, a0);  a1 = fma2(o2r[7],  w3.y, a1);
        a0 = fma2(o2r[8],  w4.x, a0);  a1 = fma2(o2r[9],  w4.y, a1);
        a0 = fma2(o2r[10], w5.x, a0);  a1 = fma2(o2r[11], w5.y, a1);
        a0 = fma2(o2r[12], w6.x, a0);  a1 = fma2(o2r[13], w6.y, a1);
        a0 = fma2(o2r[14], w7.x, a0);  a1 = fma2(o2r[15], w7.y, a1);
        float2 p = unpk(add2(a0, a1));
        sout[tok * VV + v] = p.x + p.y + sbc[v];
    }
    __syncthreads();

    // coalesced float4 store (128*28 = 3584 floats = 896 float4)
    float4* op = (float4*)(out + (size_t)t0 * VV);
    const float4* sp = (const float4*)sout;
    #pragma unroll
    for (int r = 0; r < 4; r++) {
        int i = tid + r * 256;
        if (i < 896) op[i] = sp[i];
    }
}

// ---------------------------------------------------------------------------
extern "C" void kernel_launch(void* const* d_in, const int* in_sizes, int n_in,
                              void* d_out, int out_size) {
    const int*   x    = (const int*)  d_in[0];
    const float* mask = (const float*)d_in[1];
    const float* emb  = (const float*)d_in[2];
    const float* pe   = (const float*)d_in[3];
    const float* wq   = (const float*)d_in[4];
    const float* bq   = (const float*)d_in[5];
    const float* wk   = (const float*)d_in[6];
    const float* bk   = (const float*)d_in[7];
    const float* wv   = (const float*)d_in[8];
    const float* bv   = (const float*)d_in[9];
    const float* wo   = (const float*)d_in[10];
    const float* bo   = (const float*)d_in[11];
    const float* wfc  = (const float*)d_in[12];
    const float* bfc  = (const float*)d_in[13];
    float* out = (float*)d_out;

    prep_kernel<<<BB + 1, 256>>>(mask, wo, bo, wfc, bfc);
    qkv_kernel<<<(BB * SS) / 256, 256>>>(x, emb, pe, wq, bq, wk, bk, wv, bv);
    attn_kernel<<<dim3(BB * HH, NQT_MAX, NKC_MAX), 128>>>();
    finish_kernel<<<(BB * SS) / 128, 256>>>(out);
}

// round 17
// speedup vs baseline: 1.0600x; 1.0600x over previous
#include <cuda_runtime.h>

// Problem constants (fixed by the reference setup)
#define BB 64
#define SS 1024
#define DD 32
#define HH 2
#define DH 16
#define VV 28
#define LOG2E 1.44269504088896340736f
#define KC 256      // keys per split-K chunk
#define NKC_MAX 4   // max key chunks  (SS/KC)
#define NQT_MAX 8   // max 128-query tiles (SS/128)
#define TS 36       // token stage stride in floats (multiple of 4 -> aligned)

#define NQ (BB * HH * SS * DH)
#define NBF (BB * HH * SS * 8)   // u32 count for a bf16 plane (8 u32 per row)

typedef unsigned long long u64;

// Scratch (no allocations allowed -> __device__ globals), 16B-aligned
// Q and K stored row-major [bh][s][16] as PACKED BF16 hi/lo planes
__device__ __align__(16) unsigned g_Qh[NBF];
__device__ __align__(16) unsigned g_Ql[NBF];
__device__ __align__(16) unsigned g_Kh[NBF];
__device__ __align__(16) unsigned g_Kl[NBF];
__device__ __align__(16) float    g_V[NQ];    // row-major fp32
// split-K partials, tile-SoA: [bh][kc][qt][j:4][128] float4 + [bh][kc][qt][128]
__device__ __align__(16) float g_Po[(size_t)BB * HH * NKC_MAX * NQT_MAX * 128 * DH];
__device__ __align__(16) float g_Pl[(size_t)BB * HH * NKC_MAX * NQT_MAX * 128];
__device__ int   g_Lb[BB];
__device__ __align__(16) float g_wc[VV * DD];
__device__ float g_bc[VV];

// ---------------------------------------------------------------------------
// Packed f32x2 + bf16 + misc PTX helpers
// ---------------------------------------------------------------------------
__device__ __forceinline__ u64 fma2(u64 a, u64 b, u64 c) {
    u64 d; asm("fma.rn.f32x2 %0,%1,%2,%3;" : "=l"(d) : "l"(a), "l"(b), "l"(c));
    return d;
}
__device__ __forceinline__ u64 mul2(u64 a, u64 b) {
    u64 d; asm("mul.rn.f32x2 %0,%1,%2;" : "=l"(d) : "l"(a), "l"(b));
    return d;
}
__device__ __forceinline__ u64 add2(u64 a, u64 b) {
    u64 d; asm("add.rn.f32x2 %0,%1,%2;" : "=l"(d) : "l"(a), "l"(b));
    return d;
}
__device__ __forceinline__ u64 pack2(float x, float y) {
    u64 r; asm("mov.b64 %0,{%1,%2};" : "=l"(r) : "f"(x), "f"(y));
    return r;
}
__device__ __forceinline__ float2 unpk(u64 v) {
    float2 r; asm("mov.b64 {%0,%1},%2;" : "=f"(r.x), "=f"(r.y) : "l"(v));
    return r;
}
__device__ __forceinline__ float ex2(float x) {
    float r; asm("ex2.approx.f32 %0,%1;" : "=f"(r) : "f"(x));
    return r;
}
// pack two floats to bf16x2: element0(low half)=a, element1(high half)=b
__device__ __forceinline__ unsigned pkbf(float a, float b) {
    unsigned d; asm("cvt.rn.bf16x2.f32 %0,%1,%2;" : "=r"(d) : "f"(b), "f"(a));
    return d;
}
__device__ __forceinline__ float bflo(unsigned u) { return __uint_as_float(u << 16); }
__device__ __forceinline__ float bfhi(unsigned u) { return __uint_as_float(u & 0xffff0000u); }

// D += A(bf16) * B(bf16), m16n8k16, A row-major, B col-major, f32 accumulate
__device__ __forceinline__ void mma16(float& d0, float& d1, float& d2, float& d3,
                                      const unsigned a[4], unsigned b0, unsigned b1) {
    asm volatile(
        "mma.sync.aligned.m16n8k16.row.col.f32.bf16.bf16.f32 "
        "{%0,%1,%2,%3},{%4,%5,%6,%7},{%8,%9},{%0,%1,%2,%3};"
        : "+f"(d0), "+f"(d1), "+f"(d2), "+f"(d3)
        : "r"(a[0]), "r"(a[1]), "r"(a[2]), "r"(a[3]), "r"(b0), "r"(b1));
}

// ---------------------------------------------------------------------------
// K0: per-batch prefix length Lb + combined output weights wc = w_fc @ wo
// ---------------------------------------------------------------------------
__global__ void prep_kernel(const float* __restrict__ mask,
                            const float* __restrict__ wo,
                            const float* __restrict__ bo,
                            const float* __restrict__ wfc,
                            const float* __restrict__ bfc) {
    int tid = threadIdx.x;
    int bb  = blockIdx.x;
    if (bb < BB) {
        __shared__ int smax[256];
        int mx = -1;
        const float* mp = mask + bb * SS;
        for (int s = tid; s < SS; s += 256)
            if (mp[s] > 0.f) mx = max(mx, s);
        smax[tid] = mx;
        __syncthreads();
        for (int off = 128; off > 0; off >>= 1) {
            if (tid < off) smax[tid] = max(smax[tid], smax[tid + off]);
            __syncthreads();
        }
        if (tid == 0) g_Lb[bb] = min(smax[0] + 4, SS - 1);
    } else {
        for (int e = tid; e < VV * DD; e += 256) {
            int v = e >> 5, d = e & 31;
            float acc = 0.f;
            #pragma unroll
            for (int t = 0; t < 32; t++)
                acc += wfc[v * 32 + t] * wo[t * 32 + d];
            g_wc[e] = acc;
        }
        if (tid < VV) {
            float acc = bfc[tid];
            #pragma unroll
            for (int t = 0; t < 32; t++)
                acc += wfc[tid * 32 + t] * bo[t];
            g_bc[tid] = acc;
        }
    }
}

// ---------------------------------------------------------------------------
// K1: QKV projections, 256 tokens/block. Q and K written as packed bf16
//     hi/lo planes (row-major, coalesced); V fp32. Q pre-scaled 0.25*log2e.
// ---------------------------------------------------------------------------
__global__ void __launch_bounds__(256) qkv_kernel(
    const int* __restrict__ x,  const float* __restrict__ emb,
    const float* __restrict__ pe,
    const float* __restrict__ wq, const float* __restrict__ bq,
    const float* __restrict__ wk, const float* __restrict__ bk,
    const float* __restrict__ wv, const float* __restrict__ bv) {

    __shared__ __align__(16) float sw[1024 + 32];
    __shared__ __align__(16) float so[256 * TS];     // 36 KB
    int tid = threadIdx.x;

    int t0 = blockIdx.x * 256;
    int b  = t0 >> 10, s0 = t0 & 1023;
    int s  = s0 + tid;
    int Lb = g_Lb[b];
    const float QSCL = 0.25f * LOG2E;
    bool live = (s < Lb);

    u64 h2[16];
    if (live) {
        int xid = x[t0 + tid];
        const float4* ep = (const float4*)(emb + xid * 32);
        const float4* pp = (const float4*)(pe + s * 32);
        #pragma unroll
        for (int j = 0; j < 8; j++) {
            float4 e4 = ep[j], p4 = pp[j];
            h2[2 * j]     = pack2(e4.x + p4.x, e4.y + p4.y);
            h2[2 * j + 1] = pack2(e4.z + p4.z, e4.w + p4.w);
        }
    }

    #pragma unroll
    for (int mtx = 0; mtx < 3; mtx++) {
        const float* wg = (mtx == 0) ? wq : ((mtx == 1) ? wk : wv);
        const float* bg = (mtx == 0) ? bq : ((mtx == 1) ? bk : bv);
        float scl = (mtx == 0) ? QSCL : 1.0f;

        for (int i = tid; i < 1024; i += 256) sw[i] = wg[i];
        if (tid < 32) sw[1024 + tid] = bg[tid];
        __syncthreads();

        if (live) {
            #pragma unroll 4
            for (int j = 0; j < 32; j++) {
                const ulonglong2* wr = (const ulonglong2*)(sw + j * 32);
                ulonglong2 w0 = wr[0], w1 = wr[1], w2 = wr[2], w3 = wr[3];
                ulonglong2 w4 = wr[4], w5 = wr[5], w6 = wr[6], w7 = wr[7];
                u64 a0 = mul2(h2[0], w0.x);
                u64 a1 = mul2(h2[1], w0.y);
                a0 = fma2(h2[2],  w1.x, a0);  a1 = fma2(h2[3],  w1.y, a1);
                a0 = fma2(h2[4],  w2.x, a0);  a1 = fma2(h2[5],  w2.y, a1);
                a0 = fma2(h2[6],  w3.x, a0);  a1 = fma2(h2[7],  w3.y, a1);
                a0 = fma2(h2[8],  w4.x, a0);  a1 = fma2(h2[9],  w4.y, a1);
                a0 = fma2(h2[10], w5.x, a0);  a1 = fma2(h2[11], w5.y, a1);
                a0 = fma2(h2[12], w6.x, a0);  a1 = fma2(h2[13], w6.y, a1);
                a0 = fma2(h2[14], w7.x, a0);  a1 = fma2(h2[15], w7.y, a1);
                float2 p = unpk(add2(a0, a1));
                so[tid * TS + j] = (p.x + p.y + sw[1024 + j]) * scl;
            }
        } else {
            #pragma unroll 4
            for (int j = 0; j < 32; j++)
                so[tid * TS + j] = sw[1024 + j] * scl;  // tail Q row; K/V unread
        }
        __syncthreads();

        if (mtx <= 1) {
            // Q or K: split each fp32 into bf16 hi + bf16 residual lo
            uint2* Hd = (uint2*)((mtx == 0) ? g_Qh : g_Kh);
            uint2* Ld = (uint2*)((mtx == 0) ? g_Ql : g_Kl);
            #pragma unroll
            for (int r = 0; r < 8; r++) {
                int i = tid + r * 256;
                int hh = i >> 10, low = i & 1023;   // low = tok*4+qq
                float4 v = *(const float4*)(so + (low >> 2) * TS + hh * 16 + (low & 3) * 4);
                unsigned h01 = pkbf(v.x, v.y);
                unsigned h23 = pkbf(v.z, v.w);
                float r0 = v.x - bflo(h01), r1 = v.y - bfhi(h01);
                float r2 = v.z - bflo(h23), r3 = v.w - bfhi(h23);
                unsigned l01 = pkbf(r0, r1);
                unsigned l23 = pkbf(r2, r3);
                size_t addr = ((size_t)(b * 2 + hh) * SS + s0) * 4 + low;
                Hd[addr] = make_uint2(h01, h23);
                Ld[addr] = make_uint2(l01, l23);
            }
        } else {
            float4* outp = (float4*)g_V;
            #pragma unroll
            for (int r = 0; r < 8; r++) {
                int i = tid + r * 256;
                int hh = i >> 10, low = i & 1023;
                outp[((size_t)(b * 2 + hh) * SS + s0) * 4 + low] =
                    *(const float4*)(so + (low >> 2) * TS + hh * 16 + (low & 3) * 4);
            }
        }
        __syncthreads();
    }
}

// ---------------------------------------------------------------------------
// K2: split-K attention. QK^T on tensor cores: bf16 m16n8k16, 3-term hi/lo
//     (qh*kh + ql*kh + qh*kl, fp32 accum => ~2^-17 score accuracy).
//     K=16 matches DH exactly -> 6 mma per 8-key slab per warp.
//     PV scalar fp32 (e fragment layout identical to validated R16 code).
//     Block = 128 threads (4 warps), tile 128q x 256k, grid early-exit.
// ---------------------------------------------------------------------------
__global__ void __launch_bounds__(128, 2) attn_kernel() {
    __shared__ __align__(16) unsigned sKh[KC * 8];    // 8 KB bf16-hi keys
    __shared__ __align__(16) unsigned sKl[KC * 8];    // 8 KB bf16-lo keys
    __shared__ __align__(16) float    sV [KC * DH];   // 16 KB fp32 values
    __shared__ __align__(16) unsigned sQh[128 * 8];   // 4 KB bf16-hi queries
    __shared__ __align__(16) unsigned sQl[128 * 8];   // 4 KB bf16-lo queries

    int bh = blockIdx.x, qt = blockIdx.y, kc = blockIdx.z;
    int b  = bh >> 1;
    int tid = threadIdx.x;
    int Lb = g_Lb[b];
    int nqt = (Lb >> 7) + 1;             // query tiles cover [0, Lb] inclusive
    int nkc = (Lb + KC - 1) >> 8;        // key chunks over [0, Lb)
    if (qt >= nqt || kc >= nkc) return;

    int k0 = kc << 8;
    int nk = min(KC, Lb - k0);

    // stage K hi/lo (zero-fill beyond nk), V, and the Q hi/lo tile
    {
        const uint4* Khg = (const uint4*)g_Kh + ((size_t)bh * SS + k0) * 2;
        const uint4* Klg = (const uint4*)g_Kl + ((size_t)bh * SS + k0) * 2;
        const float4* Vg = (const float4*)(g_V + ((size_t)bh * SS + k0) * DH);
        uint4 zu = make_uint4(0, 0, 0, 0);
        float4 zf = make_float4(0.f, 0.f, 0.f, 0.f);
        int nu = nk * 2, nf = nk * 4;
        for (int i = tid; i < KC * 2; i += 128) {
            ((uint4*)sKh)[i] = (i < nu) ? Khg[i] : zu;
            ((uint4*)sKl)[i] = (i < nu) ? Klg[i] : zu;
        }
        for (int i = tid; i < KC * 4; i += 128)
            ((float4*)sV)[i] = (i < nf) ? Vg[i] : zf;
        const uint4* Qhg = (const uint4*)g_Qh + ((size_t)bh * SS + qt * 128) * 2;
        const uint4* Qlg = (const uint4*)g_Ql + ((size_t)bh * SS + qt * 128) * 2;
        for (int i = tid; i < 256; i += 128) {
            ((uint4*)sQh)[i] = Qhg[i];
            ((uint4*)sQl)[i] = Qlg[i];
        }
    }
    __syncthreads();

    int wid = tid >> 5, lane = tid & 31;
    int gid = lane >> 2, tig = lane & 3;

    // A fragments (Q hi/lo, bf16 packed), persistent across key slabs
    unsigned Ah[2][4], Al[2][4];
    #pragma unroll
    for (int rb = 0; rb < 2; rb++) {
        int row = wid * 32 + rb * 16 + gid;
        Ah[rb][0] = sQh[row * 8 + tig];
        Ah[rb][1] = sQh[(row + 8) * 8 + tig];
        Ah[rb][2] = sQh[row * 8 + tig + 4];
        Ah[rb][3] = sQh[(row + 8) * 8 + tig + 4];
        Al[rb][0] = sQl[row * 8 + tig];
        Al[rb][1] = sQl[(row + 8) * 8 + tig];
        Al[rb][2] = sQl[row * 8 + tig + 4];
        Al[rb][3] = sQl[(row + 8) * 8 + tig + 4];
    }

    // accumulators: 4 row-slots x 16 dims (this thread's key-columns only)
    u64 o[4][8];
    float l[4] = {0.f, 0.f, 0.f, 0.f};
    #pragma unroll
    for (int ss = 0; ss < 4; ss++)
        #pragma unroll
        for (int j = 0; j < 8; j++) o[ss][j] = 0ull;

    for (int ct = 0; ct < KC / 8; ct++) {
        int key = ct * 8 + gid;
        unsigned b0h = sKh[key * 8 + tig], b1h = sKh[key * 8 + tig + 4];
        unsigned b0l = sKl[key * 8 + tig], b1l = sKl[key * 8 + tig + 4];

        // V rows for this thread's two key-columns
        int colA = ct * 8 + 2 * tig;
        const u64* va = (const u64*)(sV + colA * 16);
        const u64* vb = (const u64*)(sV + (colA + 1) * 16);
        u64 VA[8], VB[8];
        #pragma unroll
        for (int j = 0; j < 8; j++) { VA[j] = va[j]; VB[j] = vb[j]; }
        bool okA = colA < nk, okB = colA + 1 < nk;

        #pragma unroll
        for (int rb = 0; rb < 2; rb++) {
            float d0 = 0.f, d1 = 0.f, d2 = 0.f, d3 = 0.f;
            mma16(d0, d1, d2, d3, Ah[rb], b0h, b1h);   // qh*kh
            mma16(d0, d1, d2, d3, Al[rb], b0h, b1h);   // ql*kh
            mma16(d0, d1, d2, d3, Ah[rb], b0l, b1l);   // qh*kl
            float e0 = okA ? ex2(d0) : 0.f;
            float e1 = okB ? ex2(d1) : 0.f;
            float e2 = okA ? ex2(d2) : 0.f;
            float e3 = okB ? ex2(d3) : 0.f;
            l[rb * 2]     += e0 + e1;
            l[rb * 2 + 1] += e2 + e3;
            u64 e0p = pack2(e0, e0), e1p = pack2(e1, e1);
            u64 e2p = pack2(e2, e2), e3p = pack2(e3, e3);
            #pragma unroll
            for (int j = 0; j < 8; j++) {
                o[rb * 2][j]     = fma2(e0p, VA[j], fma2(e1p, VB[j], o[rb * 2][j]));
                o[rb * 2 + 1][j] = fma2(e2p, VA[j], fma2(e3p, VB[j], o[rb * 2 + 1][j]));
            }
        }
    }

    // reduce o,l across the 4 threads of each row group (butterfly in quads)
    #pragma unroll
    for (int ss = 0; ss < 4; ss++) {
        l[ss] += __shfl_xor_sync(0xffffffffu, l[ss], 1);
        l[ss] += __shfl_xor_sync(0xffffffffu, l[ss], 2);
        #pragma unroll
        for (int j = 0; j < 8; j++) {
            o[ss][j] = add2(o[ss][j], __shfl_xor_sync(0xffffffffu, o[ss][j], 1));
            o[ss][j] = add2(o[ss][j], __shfl_xor_sync(0xffffffffu, o[ss][j], 2));
        }
    }

    __syncthreads();                 // done with sV -> reuse as staging
    float* stage = sV;               // [128 rows][20 floats] = 10 KB
    if (tig == 0) {
        #pragma unroll
        for (int ss = 0; ss < 4; ss++) {
            int row = wid * 32 + (ss >> 1) * 16 + gid + (ss & 1) * 8;
            float* d = stage + row * 20;
            #pragma unroll
            for (int j = 0; j < 8; j++) {
                float2 p = unpk(o[ss][j]);
                d[2 * j] = p.x;  d[2 * j + 1] = p.y;
            }
            d[16] = l[ss];
        }
    }
    __syncthreads();

    // coalesced partial write (tile-SoA planes, deterministic slot)
    size_t slot = ((size_t)(bh * NKC_MAX + kc) * NQT_MAX + qt);
    float4* Po = (float4*)g_Po + slot * 4 * 128;
    #pragma unroll
    for (int j = 0; j < 4; j++)
        Po[j * 128 + tid] = *(const float4*)(stage + tid * 20 + j * 4);
    g_Pl[slot * 128 + tid] = stage[tid * 20 + 16];
}

// ---------------------------------------------------------------------------
// K3: finish = reduce partials + normalize + output GEMM, fused.
//     Block = 256 threads = 128 tokens (2 threads/token, one per head).
//     Tail tokens (s >= qlim) remap to representative row (Lb>>7, Lb&127).
// ---------------------------------------------------------------------------
__global__ void __launch_bounds__(256) finish_kernel(float* __restrict__ out) {
    __shared__ __align__(16) float swc[VV * DD];
    __shared__ float sbc[VV];
    __shared__ __align__(16) float stok[128 * TS];
    __shared__ __align__(16) float sout[128 * VV];

    int tid = threadIdx.x;
    for (int i = tid; i < VV * DD; i += 256) swc[i] = g_wc[i];
    if (tid < VV) sbc[tid] = g_bc[tid];

    int t0 = blockIdx.x * 128;
    int b  = t0 >> 10, s0 = t0 & 1023;
    int qt = s0 >> 7;
    int Lb = g_Lb[b];
    int nkc  = (Lb + KC - 1) >> 8;
    int qlim = ((Lb >> 7) + 1) << 7;   // rows [0, qlim) were computed

    int tok = tid >> 1, half = tid & 1;
    int bh  = b * 2 + half;
    int s   = s0 + tok;
    int qt_e, tk_e;
    if (s < qlim) { qt_e = qt;      tk_e = tok; }
    else          { qt_e = Lb >> 7; tk_e = Lb & 127; }

    // sum partials for this (token, head) -- coalesced within j-planes
    float l = 0.f;
    float4 o0 = make_float4(0, 0, 0, 0), o1 = o0, o2 = o0, o3 = o0;
    #pragma unroll 4
    for (int kc = 0; kc < nkc; kc++) {
        size_t slot = ((size_t)(bh * NKC_MAX + kc) * NQT_MAX + qt_e);
        const float4* Po = (const float4*)g_Po + slot * 4 * 128;
        float4 t0v = Po[0 * 128 + tk_e], t1v = Po[1 * 128 + tk_e];
        float4 t2v = Po[2 * 128 + tk_e], t3v = Po[3 * 128 + tk_e];
        o0.x += t0v.x; o0.y += t0v.y; o0.z += t0v.z; o0.w += t0v.w;
        o1.x += t1v.x; o1.y += t1v.y; o1.z += t1v.z; o1.w += t1v.w;
        o2.x += t2v.x; o2.y += t2v.y; o2.z += t2v.z; o2.w += t2v.w;
        o3.x += t3v.x; o3.y += t3v.y; o3.z += t3v.z; o3.w += t3v.w;
        l += g_Pl[slot * 128 + tk_e];
    }
    float inv = 1.f / l;
    float* dst = stok + tok * TS + half * 16;
    *(float4*)(dst + 0)  = make_float4(o0.x * inv, o0.y * inv, o0.z * inv, o0.w * inv);
    *(float4*)(dst + 4)  = make_float4(o1.x * inv, o1.y * inv, o1.z * inv, o1.w * inv);
    *(float4*)(dst + 8)  = make_float4(o2.x * inv, o2.y * inv, o2.z * inv, o2.w * inv);
    *(float4*)(dst + 12) = make_float4(o3.x * inv, o3.y * inv, o3.z * inv, o3.w * inv);
    __syncthreads();

    // output GEMM: each half computes 14 full-width outputs
    u64 o2r[16];
    const u64* src = (const u64*)(stok + tok * TS);
    #pragma unroll
    for (int j = 0; j < 16; j++) o2r[j] = src[j];

    #pragma unroll 2
    for (int vi = 0; vi < 14; vi++) {
        int v = half * 14 + vi;
        const ulonglong2* wr = (const ulonglong2*)(swc + v * 32);
        ulonglong2 w0 = wr[0], w1 = wr[1], w2 = wr[2], w3 = wr[3];
        ulonglong2 w4 = wr[4], w5 = wr[5], w6 = wr[6], w7 = wr[7];
        u64 a0 = mul2(o2r[0], w0.x);
        u64 a1 = mul2(o2r[1], w0.y);
        a0 = fma2(o2r[2],  w1.x, a0);  a1 = fma2(o2r[3],  w1.y, a1);
        a0 = fma2(o2r[4],  w2.x, a0);  a1 = fma2(o2r[5],  w2.y, a1);
        a0 = fma2(o2r[6],  w3.x, a0);  a1 = fma2(o2r[7],  w3.y, a1);
        a0 = fma2(o2r[8],  w4.x, a0);  a1 = fma2(o2r[9],  w4.y, a1);
        a0 = fma2(o2r[10], w5.x, a0);  a1 = fma2(o2r[11], w5.y, a1);
        a0 = fma2(o2r[12], w6.x, a0);  a1 = fma2(o2r[13], w6.y, a1);
        a0 = fma2(o2r[14], w7.x, a0);  a1 = fma2(o2r[15], w7.y, a1);
        float2 p = unpk(add2(a0, a1));
        sout[tok * VV + v] = p.x + p.y + sbc[v];
    }
    __syncthreads();

    // coalesced float4 store (128*28 = 3584 floats = 896 float4)
    float4* op = (float4*)(out + (size_t)t0 * VV);
    const float4* sp = (const float4*)sout;
    #pragma unroll
    for (int r = 0; r < 4; r++) {
        int i = tid + r * 256;
        if (i < 896) op[i] = sp[i];
    }
}

// ---------------------------------------------------------------------------
extern "C" void kernel_launch(void* const* d_in, const int* in_sizes, int n_in,
                              void* d_out, int out_size) {
    const int*   x    = (const int*)  d_in[0];
    const float* mask = (const float*)d_in[1];
    const float* emb  = (const float*)d_in[2];
    const float* pe   = (const float*)d_in[3];
    const float* wq   = (const float*)d_in[4];
    const float* bq   = (const float*)d_in[5];
    const float* wk   = (const float*)d_in[6];
    const float* bk   = (const float*)d_in[7];
    const float* wv   = (const float*)d_in[8];
    const float* bv   = (const float*)d_in[9];
    const float* wo   = (const float*)d_in[10];
    const float* bo   = (const float*)d_in[11];
    const float* wfc  = (const float*)d_in[12];
    const float* bfc  = (const float*)d_in[13];
    float* out = (float*)d_out;

    prep_kernel<<<BB + 1, 256>>>(mask, wo, bo, wfc, bfc);
    qkv_kernel<<<(BB * SS) / 256, 256>>>(x, emb, pe, wq, bq, wk, bk, wv, bv);
    attn_kernel<<<dim3(BB * HH, NQT_MAX, NKC_MAX), 128>>>();
    finish_kernel<<<(BB * SS) / 128, 256>>>(out);
}